// round 1
// baseline (speedup 1.0000x reference)
#include <cuda_runtime.h>
#include <cstdint>

// ---------------------------------------------------------------------------
// Problem constants (fixed by setup_inputs: B=4, C=32, H=W=128, scale=2)
// ---------------------------------------------------------------------------
#define Bn    4
#define Cn    32
#define Hn    128
#define Wn    128
#define HOn   256
#define WOn   256
#define QPB   (HOn * WOn)          // 65536 queries per batch image
#define NQ    (Bn * QPB)           // 262144 total queries
#define MTILE 64                   // queries per CTA
#define NCTA  (NQ / MTILE)         // 4096
#define ROWS66 66                  // padded row stride (floats) for smem tiles

// channels-last copy of x: [B, H, W, C]
__device__ float g_xt[Bn * Hn * Wn * Cn];

// ---------------------------------------------------------------------------
// Transpose kernel: x[B,C,H,W] -> g_xt[B,H,W,C]
// one block per (b,y) row; coalesced both directions through smem tile
// ---------------------------------------------------------------------------
__global__ void xt_kernel(const float* __restrict__ x) {
    __shared__ float s[Cn][Wn + 1];
    const int by = blockIdx.x;          // b*128 + y
    const int tid = threadIdx.x;        // 256 threads
#pragma unroll
    for (int it = 0; it < 16; ++it) {
        int idx = tid + it * 256;       // 0..4095
        int c = idx >> 7;               // 0..31
        int xc = idx & 127;
        // x[((b*32+c)*128+y)*128+xc] with by=b*128+y:
        int b = by >> 7, y = by & 127;
        s[c][xc] = x[((b * Cn + c) * Hn + y) * Wn + xc];
    }
    __syncthreads();
#pragma unroll
    for (int it = 0; it < 16; ++it) {
        int idx = tid + it * 256;
        int xc = idx >> 5;              // 0..127
        int c = idx & 31;
        g_xt[(by * Wn + xc) * Cn + c] = s[c][xc];
    }
}

// ---------------------------------------------------------------------------
// Bicubic helpers (torch aten formulation, A = -0.75)
// ---------------------------------------------------------------------------
__device__ __forceinline__ void prep_axis(float g, int& i0, float w[4]) {
    float p = ((g + 1.0f) * 128.0f - 1.0f) * 0.5f;
    float fp = floorf(p);
    i0 = (int)fp;
    float t = p - fp;
    const float A = -0.75f;
    float xx = t + 1.0f;
    w[0] = ((A * xx - 5.0f * A) * xx + 8.0f * A) * xx - 4.0f * A;
    w[1] = ((A + 2.0f) * t - (A + 3.0f)) * t * t + 1.0f;
    float s = 1.0f - t;
    w[2] = ((A + 2.0f) * s - (A + 3.0f)) * s * s + 1.0f;
    w[3] = 1.0f - w[0] - w[1] - w[2];
}

// sample one channel (=lane) with zero padding outside [0,128)
__device__ __forceinline__ float sample_c(const float* __restrict__ xb, int lane,
                                          int ix0, int iy0,
                                          const float* wx, const float* wy) {
    float acc = 0.0f;
#pragma unroll
    for (int i = 0; i < 4; ++i) {
        int yi = iy0 - 1 + i;
        if ((unsigned)yi < 128u) {
            const float* rp = xb + yi * (Wn * Cn) + lane;
            float r = 0.0f;
#pragma unroll
            for (int j = 0; j < 4; ++j) {
                int xj = ix0 - 1 + j;
                if ((unsigned)xj < 128u) r = fmaf(wx[j], __ldg(rp + xj * Cn), r);
            }
            acc = fmaf(wy[i], r, acc);
        }
    }
    return acc;
}

// ---------------------------------------------------------------------------
// Shared-memory GEMM tile: out[n][m] = relu?(in[k][m]^T @ w[k][n] + b[n])
//   in  : smem, layout [K][ROWS66] (m along the row)
//   w   : global row-major [K][N]
//   out : smem, layout [N][ROWS66]
// Thread mapping: warp 'wid' owns N/8 consecutive columns; lane owns query
// pair (2*lane, 2*lane+1). 64 FFMAs per k-step for N=256.
// ---------------------------------------------------------------------------
template <int K, int N, bool RELU>
__device__ __forceinline__ void gemm_tile(const float* __restrict__ in,
                                          const float* __restrict__ w,
                                          const float* __restrict__ bias,
                                          float* __restrict__ outT) {
    const int lane = threadIdx.x & 31;
    const int wid = threadIdx.x >> 5;
    constexpr int NW = N / 8;
    const int n0 = wid * NW;
    float acc0[NW], acc1[NW];
#pragma unroll
    for (int c = 0; c < NW; ++c) { acc0[c] = 0.0f; acc1[c] = 0.0f; }
    const float* ip = in + 2 * lane;
#pragma unroll 4
    for (int k = 0; k < K; ++k) {
        float2 a = *reinterpret_cast<const float2*>(ip + k * ROWS66);
        const float4* wr = reinterpret_cast<const float4*>(w + k * N + n0);
#pragma unroll
        for (int c4 = 0; c4 < NW / 4; ++c4) {
            float4 wv = __ldg(wr + c4);
            acc0[c4 * 4 + 0] = fmaf(a.x, wv.x, acc0[c4 * 4 + 0]);
            acc0[c4 * 4 + 1] = fmaf(a.x, wv.y, acc0[c4 * 4 + 1]);
            acc0[c4 * 4 + 2] = fmaf(a.x, wv.z, acc0[c4 * 4 + 2]);
            acc0[c4 * 4 + 3] = fmaf(a.x, wv.w, acc0[c4 * 4 + 3]);
            acc1[c4 * 4 + 0] = fmaf(a.y, wv.x, acc1[c4 * 4 + 0]);
            acc1[c4 * 4 + 1] = fmaf(a.y, wv.y, acc1[c4 * 4 + 1]);
            acc1[c4 * 4 + 2] = fmaf(a.y, wv.z, acc1[c4 * 4 + 2]);
            acc1[c4 * 4 + 3] = fmaf(a.y, wv.w, acc1[c4 * 4 + 3]);
        }
    }
#pragma unroll
    for (int c = 0; c < NW; ++c) {
        float bz = __ldg(bias + n0 + c);
        float v0 = acc0[c] + bz;
        float v1 = acc1[c] + bz;
        if (RELU) { v0 = fmaxf(v0, 0.0f); v1 = fmaxf(v1, 0.0f); }
        *reinterpret_cast<float2*>(outT + (n0 + c) * ROWS66 + 2 * lane) =
            make_float2(v0, v1);
    }
}

// ---------------------------------------------------------------------------
// Fused main kernel: one CTA = 64 consecutive queries of one batch image.
// ---------------------------------------------------------------------------
#define SMEM_FLOATS ((36 + 256 + 256 + 32 + 32) * ROWS66 + 128)
#define SMEM_BYTES  (SMEM_FLOATS * 4)

__global__ __launch_bounds__(256, 1) void fused_kernel(
    const float* __restrict__ w0, const float* __restrict__ b0,
    const float* __restrict__ w1, const float* __restrict__ b1,
    const float* __restrict__ w2, const float* __restrict__ b2,
    const float* __restrict__ rw0, const float* __restrict__ rb0,
    const float* __restrict__ rw1, const float* __restrict__ rb1,
    const float* __restrict__ ow0, const float* __restrict__ ob0,
    const float* __restrict__ ow1, const float* __restrict__ ob1,
    float* __restrict__ out) {
    extern __shared__ float sm[];
    float* inpT = sm;                        // [36][66]   (also reused as out stage)
    float* bufA = inpT + 36 * ROWS66;        // [256][66]
    float* bufB = bufA + 256 * ROWS66;       // [256][66]
    float* predT = bufB + 256 * ROWS66;      // [32][66]
    float* routT = predT + 32 * ROWS66;      // [32][66]
    float* offs = routT + 32 * ROWS66;       // [64][2]

    const int tid = threadIdx.x;
    const int lane = tid & 31;
    const int wid = tid >> 5;
    const int q0 = blockIdx.x * MTILE;       // global query base
    const int b = q0 >> 16;                  // batch index (QPB = 65536)
    const int qbase = q0 & (QPB - 1);
    const float* xb = g_xt + b * (Hn * Wn * Cn);

    // ---------------- Stage A: build inp[m][36] (stored transposed) ----------
#pragma unroll 1
    for (int i = 0; i < 8; ++i) {
        int m = wid * 8 + i;
        int ql = qbase + m;
        int oy = ql >> 8, ox = ql & 255;
        float gy = (2.0f * oy + 1.0f) * (1.0f / 256.0f) - 1.0f;
        float gx = (2.0f * ox + 1.0f) * (1.0f / 256.0f) - 1.0f;
        int ix0, iy0;
        float wx[4], wy[4];
        prep_axis(gx, ix0, wx);
        prep_axis(gy, iy0, wy);
        float qf = sample_c(xb, lane, ix0, iy0, wx, wy);
        inpT[lane * ROWS66 + m] = qf;
        if (lane == 0) {
            // closed-form bicubic sample of the coordinate field (separable)
            float syw = 0.0f, sy = 0.0f, sxw = 0.0f, sx = 0.0f;
#pragma unroll
            for (int ii = 0; ii < 4; ++ii) {
                int yi = iy0 - 1 + ii;
                if ((unsigned)yi < 128u) {
                    float yco = (2.0f * yi + 1.0f) * (1.0f / 128.0f) - 1.0f;
                    syw += wy[ii];
                    sy = fmaf(wy[ii], yco, sy);
                }
            }
#pragma unroll
            for (int jj = 0; jj < 4; ++jj) {
                int xj = ix0 - 1 + jj;
                if ((unsigned)xj < 128u) {
                    float xco = (2.0f * xj + 1.0f) * (1.0f / 128.0f) - 1.0f;
                    sxw += wx[jj];
                    sx = fmaf(wx[jj], xco, sx);
                }
            }
            float qcy = sy * sxw;
            float qcx = sx * syw;
            inpT[32 * ROWS66 + m] = (gy - qcy) * 128.0f;
            inpT[33 * ROWS66 + m] = (gx - qcx) * 128.0f;
            // cell[:,0] and cell[:,1] index the QUERY dim (faithful quirk):
            // queries 0 and 1 of each image get cell=2/256 -> rel_cell = 1.0
            float rc = (ql < 2) ? 1.0f : 128.0f;
            inpT[34 * ROWS66 + m] = rc;
            inpT[35 * ROWS66 + m] = rc;
        }
    }
    __syncthreads();

    // ---------------- MLP chain --------------------------------------------
    gemm_tile<36, 256, true>(inpT, w0, b0, bufA);    // h1
    __syncthreads();
    gemm_tile<256, 256, true>(bufA, w1, b1, bufB);   // h2
    __syncthreads();
    gemm_tile<256, 32, false>(bufB, w2, b2, predT);  // pred
    __syncthreads();
    gemm_tile<32, 256, true>(predT, rw0, rb0, bufA); // routing hidden
    __syncthreads();
    gemm_tile<256, 32, false>(bufA, rw1, rb1, routT); // routing
    __syncthreads();
    gemm_tile<32, 256, true>(predT, ow0, ob0, bufB); // offset hidden
    __syncthreads();

    // offset head: N=2, handled by 128 threads (m = tid/2, component = tid&1)
    if (tid < 128) {
        int m = tid >> 1, comp = tid & 1;
        const float* bb = bufB + m;
        float a0 = 0.f, a1 = 0.f, a2 = 0.f, a3 = 0.f;
#pragma unroll 4
        for (int k = 0; k < 256; k += 4) {
            a0 = fmaf(bb[(k + 0) * ROWS66], __ldg(ow1 + (k + 0) * 2 + comp), a0);
            a1 = fmaf(bb[(k + 1) * ROWS66], __ldg(ow1 + (k + 1) * 2 + comp), a1);
            a2 = fmaf(bb[(k + 2) * ROWS66], __ldg(ow1 + (k + 2) * 2 + comp), a2);
            a3 = fmaf(bb[(k + 3) * ROWS66], __ldg(ow1 + (k + 3) * 2 + comp), a3);
        }
        offs[m * 2 + comp] = (a0 + a1) + (a2 + a3) + __ldg(ob1 + comp);
    }
    __syncthreads();

    // ---------------- Stage C: offset resample + modulate -------------------
#pragma unroll 1
    for (int i = 0; i < 8; ++i) {
        int m = wid * 8 + i;
        int ql = qbase + m;
        int oy = ql >> 8, ox = ql & 255;
        float gy = (2.0f * oy + 1.0f) * (1.0f / 256.0f) - 1.0f;
        float gx = (2.0f * ox + 1.0f) * (1.0f / 256.0f) - 1.0f;
        float gx2 = gx + offs[m * 2 + 0];
        float gy2 = gy + offs[m * 2 + 1];
        int ix0, iy0;
        float wx[4], wy[4];
        prep_axis(gx2, ix0, wx);
        prep_axis(gy2, iy0, wy);
        float v = sample_c(xb, lane, ix0, iy0, wx, wy);
        float r = routT[lane * ROWS66 + m];
        inpT[lane * ROWS66 + m] = v * (1.0f + r);    // reuse inpT as staging
    }
    __syncthreads();

    // coalesced writeout: out[(b*32+c)*65536 + qbase + m]
    {
        int c = tid >> 3;
        int part = tid & 7;
        const float* src = inpT + c * ROWS66 + part * 8;
        float* dst = out + ((size_t)(b * Cn + c)) * QPB + qbase + part * 8;
#pragma unroll
        for (int u = 0; u < 8; ++u) dst[u] = src[u];
    }
}

// ---------------------------------------------------------------------------
// kernel_launch
// inputs: x, mlp_w0, mlp_b0, mlp_w1, mlp_b1, mlp_w2, mlp_b2,
//         rout_w0, rout_b0, rout_w1, rout_b1, off_w0, off_b0, off_w1, off_b1, scale
// ---------------------------------------------------------------------------
extern "C" void kernel_launch(void* const* d_in, const int* in_sizes, int n_in,
                              void* d_out, int out_size) {
    const float* x = (const float*)d_in[0];
    const float* w0 = (const float*)d_in[1];
    const float* b0 = (const float*)d_in[2];
    const float* w1 = (const float*)d_in[3];
    const float* b1 = (const float*)d_in[4];
    const float* w2 = (const float*)d_in[5];
    const float* b2 = (const float*)d_in[6];
    const float* rw0 = (const float*)d_in[7];
    const float* rb0 = (const float*)d_in[8];
    const float* rw1 = (const float*)d_in[9];
    const float* rb1 = (const float*)d_in[10];
    const float* ow0 = (const float*)d_in[11];
    const float* ob0 = (const float*)d_in[12];
    const float* ow1 = (const float*)d_in[13];
    const float* ob1 = (const float*)d_in[14];
    float* out = (float*)d_out;

    cudaFuncSetAttribute(fused_kernel,
                         cudaFuncAttributeMaxDynamicSharedMemorySize, SMEM_BYTES);

    xt_kernel<<<Bn * Hn, 256>>>(x);
    fused_kernel<<<NCTA, 256, SMEM_BYTES>>>(w0, b0, w1, b1, w2, b2,
                                            rw0, rb0, rw1, rb1,
                                            ow0, ob0, ow1, ob1, out);
}

// round 2
// speedup vs baseline: 1.7225x; 1.7225x over previous
#include <cuda_runtime.h>
#include <cstdint>

typedef unsigned long long ull;

// ---------------------------------------------------------------------------
// Problem constants (fixed by setup_inputs: B=4, C=32, H=W=128, scale=2)
// ---------------------------------------------------------------------------
#define Bn    4
#define Cn    32
#define Hn    128
#define Wn    128
#define QPB   65536                // 256*256 queries per image
#define NQ    (Bn * QPB)
#define MTILE 64                   // queries per CTA
#define NCTA  (NQ / MTILE)         // 4096
#define STR   68                   // padded row stride (floats), 16B-aligned

// channels-last copy of x: [B, H, W, C]
__device__ float g_xt[Bn * Hn * Wn * Cn];

// ---------------------------------------------------------------------------
// Transpose kernel: x[B,C,H,W] -> g_xt[B,H,W,C]
// ---------------------------------------------------------------------------
__global__ void xt_kernel(const float* __restrict__ x) {
    __shared__ float s[Cn][Wn + 1];
    const int by = blockIdx.x;          // b*128 + y
    const int tid = threadIdx.x;        // 256 threads
#pragma unroll
    for (int it = 0; it < 16; ++it) {
        int idx = tid + it * 256;
        int c = idx >> 7;
        int xc = idx & 127;
        int b = by >> 7, y = by & 127;
        s[c][xc] = x[((b * Cn + c) * Hn + y) * Wn + xc];
    }
    __syncthreads();
#pragma unroll
    for (int it = 0; it < 16; ++it) {
        int idx = tid + it * 256;
        int xc = idx >> 5;
        int c = idx & 31;
        g_xt[(by * Wn + xc) * Cn + c] = s[c][xc];
    }
}

// ---------------------------------------------------------------------------
// Packed f32x2 helpers (sm_103a full-rate dual FMA; ptxas never auto-emits)
// ---------------------------------------------------------------------------
__device__ __forceinline__ ull ffma2(ull a, ull b, ull c) {
    ull d;
    asm("fma.rn.f32x2 %0, %1, %2, %3;" : "=l"(d) : "l"(a), "l"(b), "l"(c));
    return d;
}
__device__ __forceinline__ ull rep2(float a) {
    ull d;
    asm("mov.b64 %0, {%1, %1};" : "=l"(d) : "f"(a));
    return d;
}
__device__ __forceinline__ float2 unpack2(ull v) {
    float2 r;
    asm("mov.b64 {%0, %1}, %2;" : "=f"(r.x), "=f"(r.y) : "l"(v));
    return r;
}

// ---------------------------------------------------------------------------
// Bicubic helpers (torch aten formulation, A = -0.75)
// ---------------------------------------------------------------------------
__device__ __forceinline__ void prep_axis(float g, int& i0, float w[4]) {
    float p = ((g + 1.0f) * 128.0f - 1.0f) * 0.5f;
    float fp = floorf(p);
    i0 = (int)fp;
    float t = p - fp;
    const float A = -0.75f;
    float xx = t + 1.0f;
    w[0] = ((A * xx - 5.0f * A) * xx + 8.0f * A) * xx - 4.0f * A;
    w[1] = ((A + 2.0f) * t - (A + 3.0f)) * t * t + 1.0f;
    float s = 1.0f - t;
    w[2] = ((A + 2.0f) * s - (A + 3.0f)) * s * s + 1.0f;
    w[3] = 1.0f - w[0] - w[1] - w[2];
}

__device__ __forceinline__ float sample_c(const float* __restrict__ xb, int lane,
                                          int ix0, int iy0,
                                          const float* wx, const float* wy) {
    float acc = 0.0f;
#pragma unroll
    for (int i = 0; i < 4; ++i) {
        int yi = iy0 - 1 + i;
        if ((unsigned)yi < 128u) {
            const float* rp = xb + yi * (Wn * Cn) + lane;
            float r = 0.0f;
#pragma unroll
            for (int j = 0; j < 4; ++j) {
                int xj = ix0 - 1 + j;
                if ((unsigned)xj < 128u) r = fmaf(wx[j], __ldg(rp + xj * Cn), r);
            }
            acc = fmaf(wy[i], r, acc);
        }
    }
    return acc;
}

// ---------------------------------------------------------------------------
// Shared-memory GEMM tile with f32x2 packed math.
//   in   : smem [K][STR] (queries m along the row)
//   w    : global row-major [K][N]
//   outT : smem [N][STR]   (may alias `in` — internal sync before writes)
// Thread tile: 4 M (float4 of acts) x NT columns (NT/2 f32x2 pairs along N).
// Warp: 16 M-groups x 2 N-groups; 8 warps cover N.
// ---------------------------------------------------------------------------
template <int K, int N, bool RELU>
__device__ __forceinline__ void gemm_tile(const float* __restrict__ in,
                                          const float* __restrict__ w,
                                          const float* __restrict__ bias,
                                          float* __restrict__ outT) {
    const int lane = threadIdx.x & 31;
    const int wid  = threadIdx.x >> 5;
    constexpr int NW = N / 8;      // columns per warp
    constexpr int NT = NW / 2;     // columns per thread
    constexpr int NP = NT / 2;     // f32x2 pairs per thread
    const int m0 = (lane & 15) * 4;
    const int n0 = wid * NW + (lane >> 4) * NT;

    ull acc[4][NP];
#pragma unroll
    for (int mi = 0; mi < 4; ++mi)
#pragma unroll
        for (int p = 0; p < NP; ++p) acc[mi][p] = 0ull;

    const float* ip = in + m0;
    const float* wp = w + n0;
#pragma unroll 4
    for (int k = 0; k < K; ++k) {
        float4 a4 = *reinterpret_cast<const float4*>(ip + k * STR);
        ull ar[4];
        ar[0] = rep2(a4.x); ar[1] = rep2(a4.y);
        ar[2] = rep2(a4.z); ar[3] = rep2(a4.w);
        ull wr[NP];
        if constexpr (NP >= 2) {
#pragma unroll
            for (int q = 0; q < NP / 2; ++q) {
                ulonglong2 wv = __ldg(
                    reinterpret_cast<const ulonglong2*>(wp + k * N + q * 4));
                wr[2 * q] = wv.x;
                wr[2 * q + 1] = wv.y;
            }
        } else {
            wr[0] = __ldg(reinterpret_cast<const ull*>(wp + k * N));
        }
#pragma unroll
        for (int mi = 0; mi < 4; ++mi)
#pragma unroll
            for (int p = 0; p < NP; ++p)
                acc[mi][p] = ffma2(ar[mi], wr[p], acc[mi][p]);
    }

    __syncthreads();   // all reads of `in` done -> safe to alias outT with in

#pragma unroll
    for (int p = 0; p < NP; ++p) {
        float bz0 = __ldg(bias + n0 + 2 * p);
        float bz1 = __ldg(bias + n0 + 2 * p + 1);
        float4 v0, v1;
        float2 u;
        u = unpack2(acc[0][p]); v0.x = u.x + bz0; v1.x = u.y + bz1;
        u = unpack2(acc[1][p]); v0.y = u.x + bz0; v1.y = u.y + bz1;
        u = unpack2(acc[2][p]); v0.z = u.x + bz0; v1.z = u.y + bz1;
        u = unpack2(acc[3][p]); v0.w = u.x + bz0; v1.w = u.y + bz1;
        if (RELU) {
            v0.x = fmaxf(v0.x, 0.f); v0.y = fmaxf(v0.y, 0.f);
            v0.z = fmaxf(v0.z, 0.f); v0.w = fmaxf(v0.w, 0.f);
            v1.x = fmaxf(v1.x, 0.f); v1.y = fmaxf(v1.y, 0.f);
            v1.z = fmaxf(v1.z, 0.f); v1.w = fmaxf(v1.w, 0.f);
        }
        *reinterpret_cast<float4*>(outT + (n0 + 2 * p) * STR + m0) = v0;
        *reinterpret_cast<float4*>(outT + (n0 + 2 * p + 1) * STR + m0) = v1;
    }
}

// ---------------------------------------------------------------------------
// Fused main kernel: one CTA = 64 consecutive queries of one batch image.
// smem ~97 KB -> 2 CTAs/SM.
// ---------------------------------------------------------------------------
#define SMEM_FLOATS ((36 + 256 + 32 + 32) * STR + 128)
#define SMEM_BYTES  (SMEM_FLOATS * 4)

__global__ __launch_bounds__(256, 2) void fused_kernel(
    const float* __restrict__ w0, const float* __restrict__ b0,
    const float* __restrict__ w1, const float* __restrict__ b1,
    const float* __restrict__ w2, const float* __restrict__ b2,
    const float* __restrict__ rw0, const float* __restrict__ rb0,
    const float* __restrict__ rw1, const float* __restrict__ rb1,
    const float* __restrict__ ow0, const float* __restrict__ ob0,
    const float* __restrict__ ow1, const float* __restrict__ ob1,
    float* __restrict__ out) {
    extern __shared__ float sm[];
    float* inpT  = sm;                       // [36][STR]  (reused as out stage)
    float* bufA  = inpT + 36 * STR;          // [256][STR] (in-place reused)
    float* predT = bufA + 256 * STR;         // [32][STR]
    float* routT = predT + 32 * STR;         // [32][STR]
    float* offs  = routT + 32 * STR;         // [64][2]

    const int tid = threadIdx.x;
    const int lane = tid & 31;
    const int wid = tid >> 5;
    const int q0 = blockIdx.x * MTILE;
    const int b = q0 >> 16;                  // QPB = 65536
    const int qbase = q0 & (QPB - 1);
    const float* xb = g_xt + b * (Hn * Wn * Cn);

    // ---------------- Stage A: build inp[m][36] (stored transposed) ---------
#pragma unroll 1
    for (int i = 0; i < 8; ++i) {
        int m = wid * 8 + i;
        int ql = qbase + m;
        int oy = ql >> 8, ox = ql & 255;
        float gy = (2.0f * oy + 1.0f) * (1.0f / 256.0f) - 1.0f;
        float gx = (2.0f * ox + 1.0f) * (1.0f / 256.0f) - 1.0f;
        int ix0, iy0;
        float wx[4], wy[4];
        prep_axis(gx, ix0, wx);
        prep_axis(gy, iy0, wy);
        float qf = sample_c(xb, lane, ix0, iy0, wx, wy);
        inpT[lane * STR + m] = qf;
        if (lane == 0) {
            float syw = 0.0f, sy = 0.0f, sxw = 0.0f, sx = 0.0f;
#pragma unroll
            for (int ii = 0; ii < 4; ++ii) {
                int yi = iy0 - 1 + ii;
                if ((unsigned)yi < 128u) {
                    float yco = (2.0f * yi + 1.0f) * (1.0f / 128.0f) - 1.0f;
                    syw += wy[ii];
                    sy = fmaf(wy[ii], yco, sy);
                }
            }
#pragma unroll
            for (int jj = 0; jj < 4; ++jj) {
                int xj = ix0 - 1 + jj;
                if ((unsigned)xj < 128u) {
                    float xco = (2.0f * xj + 1.0f) * (1.0f / 128.0f) - 1.0f;
                    sxw += wx[jj];
                    sx = fmaf(wx[jj], xco, sx);
                }
            }
            float qcy = sy * sxw;
            float qcx = sx * syw;
            inpT[32 * STR + m] = (gy - qcy) * 128.0f;
            inpT[33 * STR + m] = (gx - qcx) * 128.0f;
            float rc = (ql < 2) ? 1.0f : 128.0f;  // faithful cell quirk
            inpT[34 * STR + m] = rc;
            inpT[35 * STR + m] = rc;
        }
    }
    __syncthreads();

    // ---------------- MLP chain (bufA reused in place) ----------------------
    gemm_tile<36, 256, true>(inpT, w0, b0, bufA);
    __syncthreads();
    gemm_tile<256, 256, true>(bufA, w1, b1, bufA);     // in-place
    __syncthreads();
    gemm_tile<256, 32, false>(bufA, w2, b2, predT);
    __syncthreads();
    gemm_tile<32, 256, true>(predT, rw0, rb0, bufA);
    __syncthreads();
    gemm_tile<256, 32, false>(bufA, rw1, rb1, routT);
    __syncthreads();
    gemm_tile<32, 256, true>(predT, ow0, ob0, bufA);
    __syncthreads();

    // offset head: N=2 (m = tid/2, component = tid&1)
    if (tid < 128) {
        int m = tid >> 1, comp = tid & 1;
        const float* bb = bufA + m;
        float a0 = 0.f, a1 = 0.f, a2 = 0.f, a3 = 0.f;
#pragma unroll 4
        for (int k = 0; k < 256; k += 4) {
            a0 = fmaf(bb[(k + 0) * STR], __ldg(ow1 + (k + 0) * 2 + comp), a0);
            a1 = fmaf(bb[(k + 1) * STR], __ldg(ow1 + (k + 1) * 2 + comp), a1);
            a2 = fmaf(bb[(k + 2) * STR], __ldg(ow1 + (k + 2) * 2 + comp), a2);
            a3 = fmaf(bb[(k + 3) * STR], __ldg(ow1 + (k + 3) * 2 + comp), a3);
        }
        offs[m * 2 + comp] = (a0 + a1) + (a2 + a3) + __ldg(ob1 + comp);
    }
    __syncthreads();

    // ---------------- Stage C: offset resample + modulate -------------------
#pragma unroll 1
    for (int i = 0; i < 8; ++i) {
        int m = wid * 8 + i;
        int ql = qbase + m;
        int oy = ql >> 8, ox = ql & 255;
        float gy = (2.0f * oy + 1.0f) * (1.0f / 256.0f) - 1.0f;
        float gx = (2.0f * ox + 1.0f) * (1.0f / 256.0f) - 1.0f;
        float gx2 = gx + offs[m * 2 + 0];
        float gy2 = gy + offs[m * 2 + 1];
        int ix0, iy0;
        float wx[4], wy[4];
        prep_axis(gx2, ix0, wx);
        prep_axis(gy2, iy0, wy);
        float v = sample_c(xb, lane, ix0, iy0, wx, wy);
        float r = routT[lane * STR + m];
        inpT[lane * STR + m] = v * (1.0f + r);
    }
    __syncthreads();

    // coalesced writeout: out[(b*32+c)*65536 + qbase + m]
    {
        int c = tid >> 3;
        int part = tid & 7;
        const float* src = inpT + c * STR + part * 8;
        float* dst = out + ((size_t)(b * Cn + c)) * QPB + qbase + part * 8;
#pragma unroll
        for (int u = 0; u < 8; ++u) dst[u] = src[u];
    }
}

// ---------------------------------------------------------------------------
extern "C" void kernel_launch(void* const* d_in, const int* in_sizes, int n_in,
                              void* d_out, int out_size) {
    const float* x = (const float*)d_in[0];
    const float* w0 = (const float*)d_in[1];
    const float* b0 = (const float*)d_in[2];
    const float* w1 = (const float*)d_in[3];
    const float* b1 = (const float*)d_in[4];
    const float* w2 = (const float*)d_in[5];
    const float* b2 = (const float*)d_in[6];
    const float* rw0 = (const float*)d_in[7];
    const float* rb0 = (const float*)d_in[8];
    const float* rw1 = (const float*)d_in[9];
    const float* rb1 = (const float*)d_in[10];
    const float* ow0 = (const float*)d_in[11];
    const float* ob0 = (const float*)d_in[12];
    const float* ow1 = (const float*)d_in[13];
    const float* ob1 = (const float*)d_in[14];
    float* out = (float*)d_out;

    cudaFuncSetAttribute(fused_kernel,
                         cudaFuncAttributeMaxDynamicSharedMemorySize, SMEM_BYTES);

    xt_kernel<<<Bn * Hn, 256>>>(x);
    fused_kernel<<<NCTA, 256, SMEM_BYTES>>>(w0, b0, w1, b1, w2, b2,
                                            rw0, rb0, rw1, rb1,
                                            ow0, ob0, ow1, ob1, out);
}